// round 10
// baseline (speedup 1.0000x reference)
#include <cuda_runtime.h>
#include <cuda_bf16.h>
#include <cstdint>

// Problem constants
#define BATCH       256
#define DIM         256
#define NUM_TRUE    1024
#define NUM_SAMPLED 16384
#define LOG_RANGE   11.5129354649202280f

// GEMM tiling (bf16 tensor core): block tile 128(m) x 64(n), k-tiles of 32
#define BM   128
#define BN   64
#define NKT  8
#define PAD  40                     // padded smem row (bf16): 80B stride

// ---------------- device scratch ----------------
__device__ __nv_bfloat16 g_Wg[NUM_SAMPLED * DIM];
__device__ __nv_bfloat16 g_Abf[BATCH * DIM];
__device__ float g_off_sampled[NUM_SAMPLED];

// ---------------- math helpers (mirror reference numerics) ----------------
__device__ __forceinline__ float neg_log_ec(float idf) {
    float p  = logf((idf + 2.0f) / (idf + 1.0f)) / LOG_RANGE;
    float ec = -expm1f(16384.0f * log1pf(-p));
    return -logf(ec);
}
__device__ __forceinline__ float softplus0(float l) {
    return fmaxf(l, 0.0f) + log1pf(expf(-fabsf(l)));
}
__device__ __forceinline__ float sigmoid_xent(float l, float t) {
    return fmaxf(l, 0.0f) - l * t + log1pf(expf(-fabsf(l)));
}

// ---------------- PTX helpers ----------------
__device__ __forceinline__ void ldsm_x4(uint32_t& r0, uint32_t& r1, uint32_t& r2, uint32_t& r3,
                                        uint32_t addr) {
    asm volatile("ldmatrix.sync.aligned.m8n8.x4.shared.b16 {%0,%1,%2,%3}, [%4];\n"
                 : "=r"(r0), "=r"(r1), "=r"(r2), "=r"(r3) : "r"(addr));
}
__device__ __forceinline__ void mma16816(float* c,
                                         uint32_t a0, uint32_t a1, uint32_t a2, uint32_t a3,
                                         uint32_t b0, uint32_t b1) {
    asm volatile("mma.sync.aligned.m16n8k16.row.col.f32.bf16.bf16.f32 "
                 "{%0,%1,%2,%3}, {%4,%5,%6,%7}, {%8,%9}, {%0,%1,%2,%3};\n"
                 : "+f"(c[0]), "+f"(c[1]), "+f"(c[2]), "+f"(c[3])
                 : "r"(a0), "r"(a1), "r"(a2), "r"(a3), "r"(b0), "r"(b1));
}
__device__ __forceinline__ void cp16(uint32_t smem, const void* gmem) {
    asm volatile("cp.async.cg.shared.global [%0], [%1], 16;\n"
                 :: "r"(smem), "l"(gmem));
}
__device__ __forceinline__ void cp_commit() {
    asm volatile("cp.async.commit_group;\n");
}
template <int N>
__device__ __forceinline__ void cp_wait() {
    asm volatile("cp.async.wait_group %0;\n" :: "n"(N));
}

// ---------------- kernel 0: gather+convert W, convert A, offsets, zero out ----
#define WG_UNITS (NUM_SAMPLED * (DIM / 4))
#define A_UNITS  (BATCH * (DIM / 4))
__global__ void convert_kernel(const float* __restrict__ inputs,
                               const float* __restrict__ w,
                               const float* __restrict__ bias,
                               const int*   __restrict__ sampled,
                               float*       __restrict__ out) {
    int u = blockIdx.x * blockDim.x + threadIdx.x;
    if (u < WG_UNITS) {
        int row = u >> 6, q = u & 63;
        int id = __ldg(&sampled[row]);
        float4 v = __ldg((const float4*)(w + (size_t)id * DIM) + q);
        __nv_bfloat162* dst = (__nv_bfloat162*)(g_Wg + row * DIM + q * 4);
        dst[0] = __floats2bfloat162_rn(v.x, v.y);
        dst[1] = __floats2bfloat162_rn(v.z, v.w);
        if (q == 0) g_off_sampled[row] = bias[id] + neg_log_ec((float)id);
    } else if (u < WG_UNITS + A_UNITS) {
        int u2 = u - WG_UNITS;
        int row = u2 >> 6, q = u2 & 63;
        float4 v = __ldg((const float4*)(inputs + row * DIM) + q);
        __nv_bfloat162* dst = (__nv_bfloat162*)(g_Abf + row * DIM + q * 4);
        dst[0] = __floats2bfloat162_rn(v.x, v.y);
        dst[1] = __floats2bfloat162_rn(v.z, v.w);
    } else if (u < WG_UNITS + A_UNITS + BATCH) {
        out[u - WG_UNITS - A_UNITS] = 0.0f;
    }
}

// ---------------- fused kernel -------------------------------------------
struct GemmSmem {
    __nv_bfloat16 As[2][BM][PAD];
    __nv_bfloat16 Bs[2][BN][PAD];
    float soff[BN];
    float red2[2][BM];
};
union SmemU {
    GemmSmem g;
    float tred[8];
};

__global__ __launch_bounds__(256, 4)
void fused_kernel(const float* __restrict__ A,
                  const float* __restrict__ W,
                  const float* __restrict__ bias,
                  const int*   __restrict__ labels,
                  float*       __restrict__ out) {
    __shared__ SmemU sm;
    const int blk  = blockIdx.x;
    const int tid  = threadIdx.x;
    const int lane = tid & 31;
    const int wid  = tid >> 5;

    const int role = blk % 3;       // 0,1 -> GEMM; 2 -> true
    const int base = blk / 3;       // 0..255

    if (role < 2) {
        // ================= GEMM path: tile BM=128 x BN=64 =================
        const int id = base * 2 + role;     // 0..511
        const int bn = id >> 1;
        const int bm = id & 1;
        const int m0 = bm * BM, n0 = bn * BN;

        if (tid < BN) sm.g.soff[tid] = g_off_sampled[n0 + tid];

        const int mw = (wid >> 1) * 32;
        const int nw = (wid & 1) * 32;
        const int nwarp = wid & 1;

        // loader mapping: 16B chunks; A tile 512 chunks (2/thr), B tile 256 (1/thr)
        const int lr0 = tid >> 2;   // 0..63
        const int lc  = tid & 3;
        const uint4* gA0 = (const uint4*)(g_Abf + (m0 + lr0) * DIM) + lc;
        const uint4* gA1 = (const uint4*)(g_Abf + (m0 + lr0 + 64) * DIM) + lc;
        const uint4* gB0 = (const uint4*)(g_Wg + (n0 + lr0) * DIM) + lc;

        const uint32_t sAs = (uint32_t)__cvta_generic_to_shared(&sm.g.As[0][0][0]);
        const uint32_t sBs = (uint32_t)__cvta_generic_to_shared(&sm.g.Bs[0][0][0]);
        const uint32_t abuf = BM * PAD * 2;
        const uint32_t bbuf = BN * PAD * 2;
        const uint32_t aOff0 = (lr0 * PAD + lc * 8) * 2;
        const uint32_t aOff1 = ((lr0 + 64) * PAD + lc * 8) * 2;

        float c[2][4][4];
#pragma unroll
        for (int i = 0; i < 2; i++)
#pragma unroll
            for (int j = 0; j < 4; j++)
#pragma unroll
                for (int e = 0; e < 4; e++) c[i][j][e] = 0.0f;

        // prologue: stage 0 via cp.async
        cp16(sAs + aOff0, gA0);
        cp16(sAs + aOff1, gA1);
        cp16(sBs + aOff0, gB0);
        cp_commit();

        for (int kt = 0; kt < NKT; kt++) {
            const int cur = kt & 1;
            if (kt + 1 < NKT) {
                const int nb = (kt + 1) & 1;
                cp16(sAs + nb * abuf + aOff0, gA0 + (kt + 1) * 4);
                cp16(sAs + nb * abuf + aOff1, gA1 + (kt + 1) * 4);
                cp16(sBs + nb * bbuf + aOff0, gB0 + (kt + 1) * 4);
                cp_commit();
                cp_wait<1>();
            } else {
                cp_wait<0>();
            }
            __syncthreads();

            const uint32_t baseA = sAs + cur * abuf;
            const uint32_t baseB = sBs + cur * bbuf;
#pragma unroll
            for (int ks = 0; ks < 2; ks++) {
                uint32_t a[2][4], b[2][4];
#pragma unroll
                for (int mt = 0; mt < 2; mt++) {
                    uint32_t addr = baseA +
                        ((mw + mt * 16 + (lane & 15)) * PAD + ks * 16 + (lane >> 4) * 8) * 2;
                    ldsm_x4(a[mt][0], a[mt][1], a[mt][2], a[mt][3], addr);
                }
#pragma unroll
                for (int p = 0; p < 2; p++) {
                    uint32_t addr = baseB +
                        ((nw + p * 16 + (lane & 7) + ((lane >> 4) & 1) * 8) * PAD +
                         ks * 16 + ((lane >> 3) & 1) * 8) * 2;
                    ldsm_x4(b[p][0], b[p][1], b[p][2], b[p][3], addr);
                }
#pragma unroll
                for (int mt = 0; mt < 2; mt++)
#pragma unroll
                    for (int nt = 0; nt < 4; nt++) {
                        int p = nt >> 1, h = nt & 1;
                        mma16816(c[mt][nt], a[mt][0], a[mt][1], a[mt][2], a[mt][3],
                                 b[p][h * 2], b[p][h * 2 + 1]);
                    }
            }
            __syncthreads();   // all warps done with buf `cur` before it is refilled
        }

        // epilogue: +offset, softplus, per-row sums
        float rs[4] = {0.f, 0.f, 0.f, 0.f};
#pragma unroll
        for (int mt = 0; mt < 2; mt++)
#pragma unroll
            for (int nt = 0; nt < 4; nt++) {
                int colbase = nw + nt * 8 + (lane & 3) * 2;
#pragma unroll
                for (int e = 0; e < 4; e++) {
                    float l = c[mt][nt][e] + sm.g.soff[colbase + (e & 1)];
                    rs[mt * 2 + (e >> 1)] += softplus0(l);
                }
            }
#pragma unroll
        for (int i = 0; i < 4; i++) {
            rs[i] += __shfl_xor_sync(0xffffffff, rs[i], 1);
            rs[i] += __shfl_xor_sync(0xffffffff, rs[i], 2);
        }
        if ((lane & 3) == 0) {
            int r = lane >> 2;
            sm.g.red2[nwarp][mw + r]          = rs[0];
            sm.g.red2[nwarp][mw + r + 8]      = rs[1];
            sm.g.red2[nwarp][mw + 16 + r]     = rs[2];
            sm.g.red2[nwarp][mw + 16 + r + 8] = rs[3];
        }
        __syncthreads();
        if (tid < BM)
            atomicAdd(out + m0 + tid, sm.g.red2[0][tid] + sm.g.red2[1][tid]);
    } else {
        // ================= true-logits path (2 labels/iter, pair reduce) ===
        const int b = base;

        const float4* arow = (const float4*)(A + b * DIM);
        const float4 x0 = __ldg(arow + lane);
        const float4 x1 = __ldg(arow + lane + 32);

        const int* lab_base = labels + b * NUM_TRUE + wid * 128;
        const float tt = 1.0f / (float)NUM_TRUE;

        float acc = 0.0f;
#pragma unroll 1
        for (int g = 0; g < 4; g++) {
            const int labv  = __ldg(lab_base + g * 32 + lane);
            const float offv = __ldg(bias + labv) + neg_log_ec((float)labv);
            float mylogit = 0.0f;
#pragma unroll 4
            for (int jp = 0; jp < 16; jp++) {
                int lab0 = __shfl_sync(0xffffffff, labv, jp);
                int lab1 = __shfl_sync(0xffffffff, labv, jp + 16);
                const float4* wr0 = (const float4*)(W + (size_t)lab0 * DIM);
                const float4* wr1 = (const float4*)(W + (size_t)lab1 * DIM);
                float4 u0a = __ldg(wr0 + lane);
                float4 u0b = __ldg(wr0 + lane + 32);
                float4 u1a = __ldg(wr1 + lane);
                float4 u1b = __ldg(wr1 + lane + 32);
                float d0 = u0a.x * x0.x;
                d0 = fmaf(u0a.y, x0.y, d0); d0 = fmaf(u0a.z, x0.z, d0);
                d0 = fmaf(u0a.w, x0.w, d0);
                d0 = fmaf(u0b.x, x1.x, d0); d0 = fmaf(u0b.y, x1.y, d0);
                d0 = fmaf(u0b.z, x1.z, d0); d0 = fmaf(u0b.w, x1.w, d0);
                float d1 = u1a.x * x0.x;
                d1 = fmaf(u1a.y, x0.y, d1); d1 = fmaf(u1a.z, x0.z, d1);
                d1 = fmaf(u1a.w, x0.w, d1);
                d1 = fmaf(u1b.x, x1.x, d1); d1 = fmaf(u1b.y, x1.y, d1);
                d1 = fmaf(u1b.z, x1.z, d1); d1 = fmaf(u1b.w, x1.w, d1);
                d0 += __shfl_xor_sync(0xffffffff, d0, 16);
                d1 += __shfl_xor_sync(0xffffffff, d1, 16);
                float m = (lane < 16) ? d0 : d1;
                m += __shfl_xor_sync(0xffffffff, m, 8);
                m += __shfl_xor_sync(0xffffffff, m, 4);
                m += __shfl_xor_sync(0xffffffff, m, 2);
                m += __shfl_xor_sync(0xffffffff, m, 1);
                if ((lane & 15) == jp) mylogit = m;
            }
            float l = mylogit + offv;
            acc += sigmoid_xent(l, tt);
        }
        acc += __shfl_xor_sync(0xffffffff, acc, 16);
        acc += __shfl_xor_sync(0xffffffff, acc, 8);
        acc += __shfl_xor_sync(0xffffffff, acc, 4);
        acc += __shfl_xor_sync(0xffffffff, acc, 2);
        acc += __shfl_xor_sync(0xffffffff, acc, 1);
        if (lane == 0) sm.tred[wid] = acc;
        __syncthreads();
        if (tid == 0) {
            float s = 0.0f;
#pragma unroll
            for (int i = 0; i < 8; i++) s += sm.tred[i];
            atomicAdd(out + b, s);
        }
    }
}

// ---------------- launch ---------------------------------------------------
extern "C" void kernel_launch(void* const* d_in, const int* in_sizes, int n_in,
                              void* d_out, int out_size) {
    const float* inputs  = (const float*)d_in[0];
    const float* w       = (const float*)d_in[1];
    const float* bias    = (const float*)d_in[2];
    const int*   labels  = (const int*)d_in[3];
    const int*   sampled = (const int*)d_in[4];
    float*       out     = (float*)d_out;

    const int conv_units = WG_UNITS + A_UNITS + BATCH;
    convert_kernel<<<(conv_units + 255) / 256, 256>>>(inputs, w, bias, sampled, out);
    fused_kernel<<<768, 256>>>(inputs, w, bias, labels, out);
}

// round 11
// speedup vs baseline: 1.1666x; 1.1666x over previous
#include <cuda_runtime.h>
#include <cuda_bf16.h>
#include <cstdint>

// Problem constants
#define BATCH       256
#define DIM         256
#define NUM_TRUE    1024
#define NUM_SAMPLED 16384
#define LOG_RANGE   11.5129354649202280f

// GEMM tiling (bf16 tensor core): block tile 128(m) x 64(n), k-tiles of 32
#define BM   128
#define BN   64
#define NKT  8
#define PAD  40                     // padded smem row (bf16): 80B stride

// ---------------- device scratch ----------------
__device__ __nv_bfloat16 g_Wg[NUM_SAMPLED * DIM];
__device__ __nv_bfloat16 g_Abf[BATCH * DIM];
__device__ float g_off_sampled[NUM_SAMPLED];

// ---------------- math helpers (mirror reference numerics) ----------------
__device__ __forceinline__ float neg_log_ec(float idf) {
    float p  = logf((idf + 2.0f) / (idf + 1.0f)) / LOG_RANGE;
    float ec = -expm1f(16384.0f * log1pf(-p));
    return -logf(ec);
}
__device__ __forceinline__ float softplus0(float l) {
    return fmaxf(l, 0.0f) + log1pf(expf(-fabsf(l)));
}
__device__ __forceinline__ float sigmoid_xent(float l, float t) {
    return fmaxf(l, 0.0f) - l * t + log1pf(expf(-fabsf(l)));
}

// ---------------- PTX helpers ----------------
__device__ __forceinline__ void ldsm_x4(uint32_t& r0, uint32_t& r1, uint32_t& r2, uint32_t& r3,
                                        uint32_t addr) {
    asm volatile("ldmatrix.sync.aligned.m8n8.x4.shared.b16 {%0,%1,%2,%3}, [%4];\n"
                 : "=r"(r0), "=r"(r1), "=r"(r2), "=r"(r3) : "r"(addr));
}
__device__ __forceinline__ void mma16816(float* c,
                                         uint32_t a0, uint32_t a1, uint32_t a2, uint32_t a3,
                                         uint32_t b0, uint32_t b1) {
    asm volatile("mma.sync.aligned.m16n8k16.row.col.f32.bf16.bf16.f32 "
                 "{%0,%1,%2,%3}, {%4,%5,%6,%7}, {%8,%9}, {%0,%1,%2,%3};\n"
                 : "+f"(c[0]), "+f"(c[1]), "+f"(c[2]), "+f"(c[3])
                 : "r"(a0), "r"(a1), "r"(a2), "r"(a3), "r"(b0), "r"(b1));
}

// ---------------- kernel 0: gather+convert W, convert A, offsets, zero out ----
#define WG_UNITS (NUM_SAMPLED * (DIM / 4))
#define A_UNITS  (BATCH * (DIM / 4))
__global__ void convert_kernel(const float* __restrict__ inputs,
                               const float* __restrict__ w,
                               const float* __restrict__ bias,
                               const int*   __restrict__ sampled,
                               float*       __restrict__ out) {
    int u = blockIdx.x * blockDim.x + threadIdx.x;
    if (u < WG_UNITS) {
        int row = u >> 6, q = u & 63;
        int id = __ldg(&sampled[row]);
        float4 v = __ldg((const float4*)(w + (size_t)id * DIM) + q);
        __nv_bfloat162* dst = (__nv_bfloat162*)(g_Wg + row * DIM + q * 4);
        dst[0] = __floats2bfloat162_rn(v.x, v.y);
        dst[1] = __floats2bfloat162_rn(v.z, v.w);
        if (q == 0) g_off_sampled[row] = bias[id] + neg_log_ec((float)id);
    } else if (u < WG_UNITS + A_UNITS) {
        int u2 = u - WG_UNITS;
        int row = u2 >> 6, q = u2 & 63;
        float4 v = __ldg((const float4*)(inputs + row * DIM) + q);
        __nv_bfloat162* dst = (__nv_bfloat162*)(g_Abf + row * DIM + q * 4);
        dst[0] = __floats2bfloat162_rn(v.x, v.y);
        dst[1] = __floats2bfloat162_rn(v.z, v.w);
    } else if (u < WG_UNITS + A_UNITS + BATCH) {
        out[u - WG_UNITS - A_UNITS] = 0.0f;
    }
}

// ---------------- fused kernel -------------------------------------------
struct GemmSmem {
    __nv_bfloat16 As[2][BM][PAD];
    __nv_bfloat16 Bs[2][BN][PAD];
    float soff[BN];
    float red2[2][BM];
};
union SmemU {
    GemmSmem g;
    float tred[8];
};

__global__ __launch_bounds__(256, 3)
void fused_kernel(const float* __restrict__ A,
                  const float* __restrict__ W,
                  const float* __restrict__ bias,
                  const int*   __restrict__ labels,
                  float*       __restrict__ out) {
    __shared__ SmemU sm;
    const int blk  = blockIdx.x;
    const int tid  = threadIdx.x;
    const int lane = tid & 31;
    const int wid  = tid >> 5;

    const int role = blk % 3;       // 0 -> GEMM; 1,2 -> true
    const int base = blk / 3;       // 0..511

    if (role == 0) {
        // ================= GEMM path: tile BM=128 x BN=64 =================
        const int id = base;                // 0..511
        const int bn = id >> 1;
        const int bm = id & 1;
        const int m0 = bm * BM, n0 = bn * BN;

        if (tid < BN) sm.g.soff[tid] = g_off_sampled[n0 + tid];

        const int mw = (wid >> 1) * 32;
        const int nw = (wid & 1) * 32;
        const int nwarp = wid & 1;

        const int lr0 = tid >> 2;
        const int lc  = tid & 3;
        const uint4* gA0 = (const uint4*)(g_Abf + (m0 + lr0) * DIM) + lc;
        const uint4* gA1 = (const uint4*)(g_Abf + (m0 + lr0 + 64) * DIM) + lc;
        const uint4* gB0 = (const uint4*)(g_Wg + (n0 + lr0) * DIM) + lc;

        float c[2][4][4];
#pragma unroll
        for (int i = 0; i < 2; i++)
#pragma unroll
            for (int j = 0; j < 4; j++)
#pragma unroll
                for (int e = 0; e < 4; e++) c[i][j][e] = 0.0f;

        uint4 ra0 = gA0[0], ra1 = gA1[0], rb0 = gB0[0];
        *(uint4*)&sm.g.As[0][lr0][lc * 8]      = ra0;
        *(uint4*)&sm.g.As[0][lr0 + 64][lc * 8] = ra1;
        *(uint4*)&sm.g.Bs[0][lr0][lc * 8]      = rb0;
        __syncthreads();

        const uint32_t sAs = (uint32_t)__cvta_generic_to_shared(&sm.g.As[0][0][0]);
        const uint32_t sBs = (uint32_t)__cvta_generic_to_shared(&sm.g.Bs[0][0][0]);
        const uint32_t abuf = BM * PAD * 2;
        const uint32_t bbuf = BN * PAD * 2;

        int buf = 0;
        for (int kt = 0; kt < NKT; kt++) {
            if (kt < NKT - 1) {
                ra0 = gA0[(kt + 1) * 4];
                ra1 = gA1[(kt + 1) * 4];
                rb0 = gB0[(kt + 1) * 4];
            }
            const uint32_t baseA = sAs + buf * abuf;
            const uint32_t baseB = sBs + buf * bbuf;
#pragma unroll
            for (int ks = 0; ks < 2; ks++) {
                uint32_t a[2][4], b[2][4];
#pragma unroll
                for (int mt = 0; mt < 2; mt++) {
                    uint32_t addr = baseA +
                        ((mw + mt * 16 + (lane & 15)) * PAD + ks * 16 + (lane >> 4) * 8) * 2;
                    ldsm_x4(a[mt][0], a[mt][1], a[mt][2], a[mt][3], addr);
                }
#pragma unroll
                for (int p = 0; p < 2; p++) {
                    uint32_t addr = baseB +
                        ((nw + p * 16 + (lane & 7) + ((lane >> 4) & 1) * 8) * PAD +
                         ks * 16 + ((lane >> 3) & 1) * 8) * 2;
                    ldsm_x4(b[p][0], b[p][1], b[p][2], b[p][3], addr);
                }
#pragma unroll
                for (int mt = 0; mt < 2; mt++)
#pragma unroll
                    for (int nt = 0; nt < 4; nt++) {
                        int p = nt >> 1, h = nt & 1;
                        mma16816(c[mt][nt], a[mt][0], a[mt][1], a[mt][2], a[mt][3],
                                 b[p][h * 2], b[p][h * 2 + 1]);
                    }
            }
            if (kt < NKT - 1) {
                int nb = buf ^ 1;
                *(uint4*)&sm.g.As[nb][lr0][lc * 8]      = ra0;
                *(uint4*)&sm.g.As[nb][lr0 + 64][lc * 8] = ra1;
                *(uint4*)&sm.g.Bs[nb][lr0][lc * 8]      = rb0;
                __syncthreads();
                buf = nb;
            }
        }

        float rs[4] = {0.f, 0.f, 0.f, 0.f};
#pragma unroll
        for (int mt = 0; mt < 2; mt++)
#pragma unroll
            for (int nt = 0; nt < 4; nt++) {
                int colbase = nw + nt * 8 + (lane & 3) * 2;
#pragma unroll
                for (int e = 0; e < 4; e++) {
                    float l = c[mt][nt][e] + sm.g.soff[colbase + (e & 1)];
                    rs[mt * 2 + (e >> 1)] += softplus0(l);
                }
            }
#pragma unroll
        for (int i = 0; i < 4; i++) {
            rs[i] += __shfl_xor_sync(0xffffffff, rs[i], 1);
            rs[i] += __shfl_xor_sync(0xffffffff, rs[i], 2);
        }
        if ((lane & 3) == 0) {
            int r = lane >> 2;
            sm.g.red2[nwarp][mw + r]          = rs[0];
            sm.g.red2[nwarp][mw + r + 8]      = rs[1];
            sm.g.red2[nwarp][mw + 16 + r]     = rs[2];
            sm.g.red2[nwarp][mw + 16 + r + 8] = rs[3];
        }
        __syncthreads();
        if (tid < BM)
            atomicAdd(out + m0 + tid, sm.g.red2[0][tid] + sm.g.red2[1][tid]);
    } else {
        // ===== true-logits path: 1024 blocks, each = 1/4 of a batch row =====
        const int id = base * 2 + (role - 1);   // 0..1023
        const int b  = id >> 2;                 // batch row
        const int qt = id & 3;                  // quarter

        const float4* arow = (const float4*)(A + b * DIM);
        const float4 x0 = __ldg(arow + lane);
        const float4 x1 = __ldg(arow + lane + 32);

        // warp owns 32 labels
        const int* lab_base = labels + b * NUM_TRUE + qt * 256 + wid * 32;
        const float tt = 1.0f / (float)NUM_TRUE;

        const int labv  = __ldg(lab_base + lane);
        const float offv = __ldg(bias + labv) + neg_log_ec((float)labv);
        float mylogit = 0.0f;
#pragma unroll 4
        for (int jp = 0; jp < 16; jp++) {
            int lab0 = __shfl_sync(0xffffffff, labv, jp);
            int lab1 = __shfl_sync(0xffffffff, labv, jp + 16);
            const float4* wr0 = (const float4*)(W + (size_t)lab0 * DIM);
            const float4* wr1 = (const float4*)(W + (size_t)lab1 * DIM);
            float4 u0a = __ldg(wr0 + lane);
            float4 u0b = __ldg(wr0 + lane + 32);
            float4 u1a = __ldg(wr1 + lane);
            float4 u1b = __ldg(wr1 + lane + 32);
            float d0 = u0a.x * x0.x;
            d0 = fmaf(u0a.y, x0.y, d0); d0 = fmaf(u0a.z, x0.z, d0);
            d0 = fmaf(u0a.w, x0.w, d0);
            d0 = fmaf(u0b.x, x1.x, d0); d0 = fmaf(u0b.y, x1.y, d0);
            d0 = fmaf(u0b.z, x1.z, d0); d0 = fmaf(u0b.w, x1.w, d0);
            float d1 = u1a.x * x0.x;
            d1 = fmaf(u1a.y, x0.y, d1); d1 = fmaf(u1a.z, x0.z, d1);
            d1 = fmaf(u1a.w, x0.w, d1);
            d1 = fmaf(u1b.x, x1.x, d1); d1 = fmaf(u1b.y, x1.y, d1);
            d1 = fmaf(u1b.z, x1.z, d1); d1 = fmaf(u1b.w, x1.w, d1);
            d0 += __shfl_xor_sync(0xffffffff, d0, 16);
            d1 += __shfl_xor_sync(0xffffffff, d1, 16);
            float m = (lane < 16) ? d0 : d1;
            m += __shfl_xor_sync(0xffffffff, m, 8);
            m += __shfl_xor_sync(0xffffffff, m, 4);
            m += __shfl_xor_sync(0xffffffff, m, 2);
            m += __shfl_xor_sync(0xffffffff, m, 1);
            if ((lane & 15) == jp) mylogit = m;
        }
        float acc = sigmoid_xent(mylogit + offv, tt);

        // warp reduce, then block reduce -> one atomic
        acc += __shfl_xor_sync(0xffffffff, acc, 16);
        acc += __shfl_xor_sync(0xffffffff, acc, 8);
        acc += __shfl_xor_sync(0xffffffff, acc, 4);
        acc += __shfl_xor_sync(0xffffffff, acc, 2);
        acc += __shfl_xor_sync(0xffffffff, acc, 1);
        if (lane == 0) sm.tred[wid] = acc;
        __syncthreads();
        if (tid == 0) {
            float s = 0.0f;
#pragma unroll
            for (int i = 0; i < 8; i++) s += sm.tred[i];
            atomicAdd(out + b, s);
        }
    }
}

// ---------------- launch ---------------------------------------------------
extern "C" void kernel_launch(void* const* d_in, const int* in_sizes, int n_in,
                              void* d_out, int out_size) {
    const float* inputs  = (const float*)d_in[0];
    const float* w       = (const float*)d_in[1];
    const float* bias    = (const float*)d_in[2];
    const int*   labels  = (const int*)d_in[3];
    const int*   sampled = (const int*)d_in[4];
    float*       out     = (float*)d_out;

    const int conv_units = WG_UNITS + A_UNITS + BATCH;
    convert_kernel<<<(conv_units + 255) / 256, 256>>>(inputs, w, bias, sampled, out);
    fused_kernel<<<1536, 256>>>(inputs, w, bias, labels, out);
}